// round 3
// baseline (speedup 1.0000x reference)
#include <cuda_runtime.h>

// ---------------------------------------------------------------------------
// R3: split into (1) coalesced streaming pool kernel via smem tiles,
//     (2) compute kernel (encode+circuit+head+BN partials),
//     (3) BN finalize, (4) BN apply.
// Rationale: R2 showed DRAM pinned at 41% due to 32-line-per-LDG scatter;
// coalesced staging cuts L1 wavefronts 8x and feeds DRAM a dense stream.
// ---------------------------------------------------------------------------

#define MAX_B 32768

__device__ float g_scale[4];
__device__ float g_shift[4];
__device__ float g_partial[2048 * 8];       // per-block {sum[4], sumsq[4]}
__device__ float g_pooled[MAX_B * 16];      // pooled features scratch

// ---------------- Kernel 1: avg-pool 6x6 (24x24 crop) -----------------------
// 16 samples per 256-thread block. Stage rows 0..23 (28 cols, 2688B/sample)
// into smem with fully coalesced float4 loads, then pool from smem.
__global__ __launch_bounds__(256) void pool_kernel(
    const float* __restrict__ x, int B)
{
    __shared__ float sm[16 * 672];   // 16 samples x 24 rows x 28 cols
    const int tid = threadIdx.x;
    const int b0 = blockIdx.x * 16;

    const float4* x4 = reinterpret_cast<const float4*>(x);
    float4* sm4 = reinterpret_cast<float4*>(sm);

    // copy 16 x 168 float4 (skip tail rows 24..27 of each sample)
#pragma unroll
    for (int k = 0; k < 11; ++k) {
        const int i = tid + k * 256;
        if (i < 2688) {
            const int s = i / 168;
            const int o = i - s * 168;
            const int gs = b0 + s;
            sm4[i] = (gs < B) ? __ldg(x4 + (size_t)gs * 196 + o)
                              : make_float4(0.f, 0.f, 0.f, 0.f);
        }
    }
    __syncthreads();

    // one thread per (sample, feature)
    const int s  = tid >> 4;
    const int f  = tid & 15;
    const int pr = f >> 2;
    const int pc = f & 3;
    const float* base = sm + s * 672 + pr * 6 * 28 + pc * 6;
    float acc = 0.f;
#pragma unroll
    for (int r = 0; r < 6; ++r)
#pragma unroll
        for (int c = 0; c < 6; ++c)
            acc += base[r * 28 + c];

    if (b0 + s < B)
        g_pooled[(b0 + s) * 16 + f] = acc * (1.0f / 36.0f);
}

// ---------------- circuit helpers -------------------------------------------
template <int S>
__device__ __forceinline__ void apply1q(float re[16], float im[16],
                                        float u00r, float u00i,
                                        float u01r, float u01i,
                                        float u10r, float u10i,
                                        float u11r, float u11i) {
#pragma unroll
    for (int a = 0; a < 16; ++a) {
        if (a & S) continue;
        const int b = a + S;
        const float x0r = re[a], x0i = im[a];
        const float x1r = re[b], x1i = im[b];
        re[a] = u00r * x0r - u00i * x0i + u01r * x1r - u01i * x1i;
        im[a] = u00r * x0i + u00i * x0r + u01r * x1i + u01i * x1r;
        re[b] = u10r * x0r - u10i * x0i + u11r * x1r - u11i * x1i;
        im[b] = u10r * x0i + u10i * x0r + u11r * x1i + u11i * x1r;
    }
}

template <int SC, int ST>
__device__ __forceinline__ void apply_cnot(float re[16], float im[16]) {
#pragma unroll
    for (int a = 0; a < 16; ++a) {
        if ((a & SC) && !(a & ST)) {
            const int b = a + ST;
            float t;
            t = re[a]; re[a] = re[b]; re[b] = t;
            t = im[a]; im[a] = im[b]; im[b] = t;
        }
    }
}

// ---------------- Kernel 2: encode + circuit + head + BN partials -----------
__global__ __launch_bounds__(128) void circuit_kernel(
    const float* __restrict__ enc_w,    // [4,16]
    const float* __restrict__ enc_b,    // [4]
    const float* __restrict__ qparams,  // [3,4,3]
    const float* __restrict__ cls_w,    // [4,4]
    const float* __restrict__ cls_b,    // [4]
    float* __restrict__ out,            // [B,4]
    int B)
{
    __shared__ float sg[12][8];
    __shared__ float sred[4][8];
    const int tid = threadIdx.x;
    if (tid < 12) {
        const float phi = qparams[tid * 3 + 0];
        const float th  = qparams[tid * 3 + 1];
        const float om  = qparams[tid * 3 + 2];
        float sp, cp, smn, cmn, st, ct;
        sincosf(0.5f * (phi + om), &sp, &cp);
        sincosf(0.5f * (phi - om), &smn, &cmn);
        sincosf(0.5f * th, &st, &ct);
        sg[tid][0] =  ct * cp;   sg[tid][1] = -ct * sp;    // U00
        sg[tid][2] = -st * cmn;  sg[tid][3] = -st * smn;   // U01
        sg[tid][4] =  st * cmn;  sg[tid][5] = -st * smn;   // U10
        sg[tid][6] =  ct * cp;   sg[tid][7] =  ct * sp;    // U11
    }
    __syncthreads();

    const int b = blockIdx.x * 128 + tid;
    float4 o = make_float4(0.f, 0.f, 0.f, 0.f);

    if (b < B) {
        // --- load pooled features (coalesced float4) ---
        const float4* p4 = reinterpret_cast<const float4*>(g_pooled) + b * 4;
        const float4 p0 = p4[0], p1 = p4[1], p2 = p4[2], p3 = p4[3];
        float pooled[16] = {p0.x, p0.y, p0.z, p0.w, p1.x, p1.y, p1.z, p1.w,
                            p2.x, p2.y, p2.z, p2.w, p3.x, p3.y, p3.z, p3.w};

        // --- encoder ---
        float z[4];
#pragma unroll
        for (int w = 0; w < 4; ++w) {
            float acc = __ldg(enc_b + w);
#pragma unroll
            for (int f = 0; f < 16; ++f) acc += pooled[f] * __ldg(enc_w + w * 16 + f);
            z[w] = acc;
        }

        // --- initial state: RX layer on |0000> in closed form ---
        float cw[4], sw[4];
#pragma unroll
        for (int w = 0; w < 4; ++w) __sincosf(0.5f * z[w], &sw[w], &cw[w]);

        float re[16], im[16];
#pragma unroll
        for (int idx = 0; idx < 16; ++idx) {
            const float p = (idx & 8 ? sw[0] : cw[0]) *
                            (idx & 4 ? sw[1] : cw[1]) *
                            (idx & 2 ? sw[2] : cw[2]) *
                            (idx & 1 ? sw[3] : cw[3]);
            const int m = __popc(idx) & 3;
            re[idx] = (m == 0) ? p : ((m == 2) ? -p : 0.f);
            im[idx] = (m == 1) ? -p : ((m == 3) ? p : 0.f);
        }

        // --- 3 variational layers ---
#pragma unroll
        for (int layer = 0; layer < 3; ++layer) {
            const float* g;
            g = sg[layer * 4 + 0];
            apply1q<8>(re, im, g[0], g[1], g[2], g[3], g[4], g[5], g[6], g[7]);
            g = sg[layer * 4 + 1];
            apply1q<4>(re, im, g[0], g[1], g[2], g[3], g[4], g[5], g[6], g[7]);
            g = sg[layer * 4 + 2];
            apply1q<2>(re, im, g[0], g[1], g[2], g[3], g[4], g[5], g[6], g[7]);
            g = sg[layer * 4 + 3];
            apply1q<1>(re, im, g[0], g[1], g[2], g[3], g[4], g[5], g[6], g[7]);
            apply_cnot<8, 4>(re, im);
            apply_cnot<4, 2>(re, im);
            apply_cnot<2, 1>(re, im);
        }

        // --- <Z_w> and classifier head ---
        float prob[16];
#pragma unroll
        for (int i = 0; i < 16; ++i) prob[i] = re[i] * re[i] + im[i] * im[i];

        float ev[4];
#pragma unroll
        for (int w = 0; w < 4; ++w) {
            const int s = 8 >> w;
            float e = 0.f;
#pragma unroll
            for (int i = 0; i < 16; ++i) e += (i & s) ? -prob[i] : prob[i];
            ev[w] = e;
        }

        float* op = &o.x;
#pragma unroll
        for (int oo = 0; oo < 4; ++oo) {
            float acc = __ldg(cls_b + oo);
#pragma unroll
            for (int w = 0; w < 4; ++w) acc += ev[w] * __ldg(cls_w + oo * 4 + w);
            op[oo] = acc;
        }
        reinterpret_cast<float4*>(out)[b] = o;
    }

    // --- fused BN partials (every lane is a distinct sample) ---
    float vals[8];
    vals[0] = o.x;       vals[1] = o.y;       vals[2] = o.z;       vals[3] = o.w;
    vals[4] = o.x * o.x; vals[5] = o.y * o.y; vals[6] = o.z * o.z; vals[7] = o.w * o.w;
#pragma unroll
    for (int j = 0; j < 8; ++j) {
#pragma unroll
        for (int m = 1; m < 32; m <<= 1)
            vals[j] += __shfl_xor_sync(0xffffffffu, vals[j], m);
    }
    const int warpid = tid >> 5;
    if ((tid & 31) == 0) {
#pragma unroll
        for (int j = 0; j < 8; ++j) sred[warpid][j] = vals[j];
    }
    __syncthreads();
    if (tid < 8) {
        float s = 0.f;
#pragma unroll
        for (int k = 0; k < 4; ++k) s += sred[k][tid];
        g_partial[blockIdx.x * 8 + tid] = s;
    }
}

// ---------------- Kernel 3: BN finalize --------------------------------------
__global__ __launch_bounds__(64) void bn_finalize(
    const float* __restrict__ gamma,
    const float* __restrict__ beta,
    int nblocks, int B)
{
    __shared__ float sm[8][8];
    const int tid = threadIdx.x;
    const int j = tid & 7;
    const int g = tid >> 3;
    float s = 0.f;
    for (int k = g; k < nblocks; k += 8) s += g_partial[k * 8 + j];
    sm[g][j] = s;
    __syncthreads();
    if (tid < 4) {
        float sum = 0.f, sq = 0.f;
#pragma unroll
        for (int k = 0; k < 8; ++k) { sum += sm[k][tid]; sq += sm[k][tid + 4]; }
        const float invB = 1.0f / (float)B;
        const float mu  = sum * invB;
        const float var = sq * invB - mu * mu;
        const float sc  = gamma[tid] * rsqrtf(var + 1e-5f);
        g_scale[tid] = sc;
        g_shift[tid] = beta[tid] - mu * sc;
    }
}

// ---------------- Kernel 4: BN apply ------------------------------------------
__global__ __launch_bounds__(256) void bn_apply(float* __restrict__ out, int B)
{
    const int i = blockIdx.x * blockDim.x + threadIdx.x;
    if (i < B) {
        float4 v = reinterpret_cast<float4*>(out)[i];
        v.x = v.x * g_scale[0] + g_shift[0];
        v.y = v.y * g_scale[1] + g_shift[1];
        v.z = v.z * g_scale[2] + g_shift[2];
        v.w = v.w * g_scale[3] + g_shift[3];
        reinterpret_cast<float4*>(out)[i] = v;
    }
}

extern "C" void kernel_launch(void* const* d_in, const int* in_sizes, int n_in,
                              void* d_out, int out_size)
{
    const float* x        = (const float*)d_in[0];
    const float* enc_w    = (const float*)d_in[1];
    const float* enc_b    = (const float*)d_in[2];
    const float* qparams  = (const float*)d_in[3];
    const float* cls_w    = (const float*)d_in[4];
    const float* cls_b    = (const float*)d_in[5];
    const float* bn_gamma = (const float*)d_in[6];
    const float* bn_beta  = (const float*)d_in[7];
    float* out = (float*)d_out;

    const int B = in_sizes[0] / 784;
    const int pool_blocks = (B + 15) / 16;
    const int circ_blocks = (B + 127) / 128;

    pool_kernel<<<pool_blocks, 256>>>(x, B);
    circuit_kernel<<<circ_blocks, 128>>>(enc_w, enc_b, qparams, cls_w, cls_b, out, B);
    bn_finalize<<<1, 64>>>(bn_gamma, bn_beta, circ_blocks, B);
    bn_apply<<<(B + 255) / 256, 256>>>(out, B);
}

// round 4
// speedup vs baseline: 1.3013x; 1.3013x over previous
#include <cuda_runtime.h>
#include <cstdint>

// ---------------------------------------------------------------------------
// R4: ONE fused persistent kernel.
//   - 128 persistent blocks (all co-resident), 256 samples/block
//   - cp.async double-buffered smem staging (16-sample chunks, coalesced)
//   - pool -> encode -> circuit -> head, pre-BN result held in REGISTERS
//   - software global barrier (monotonic counter, graph-replay safe)
//   - per-block redundant BN finalize, in-register apply, single out write
// ---------------------------------------------------------------------------

#define NBLK_MAX 128
#define THREADS 256

__device__ float g_partial[NBLK_MAX * 8];
__device__ unsigned g_bar = 0;

__device__ __forceinline__ uint32_t smem_u32(const void* p) {
    return (uint32_t)__cvta_generic_to_shared(p);
}

// Issue one 16-sample chunk (rows 0..23 of each sample = 168 float4) via
// cp.async into stagebuf. Always commits a group (possibly empty) so the
// wait_group bookkeeping stays uniform.
__device__ __forceinline__ void issue_chunk(
    const float4* __restrict__ x4, int b0, int cc, int B,
    float* stagebuf, int tid)
{
    if (cc < 16) {
        const int sbase = b0 + cc * 16;
#pragma unroll
        for (int k = 0; k < 11; ++k) {
            const int i = tid + k * 256;
            if (i < 2688) {
                const int s = i / 168;
                const int o = i - s * 168;
                const int gs = sbase + s;
                if (gs < B) {
                    const uint32_t d = smem_u32(stagebuf + s * 672 + o * 4);
                    const float4* src = x4 + (size_t)gs * 196 + o;
                    asm volatile("cp.async.cg.shared.global [%0], [%1], 16;"
                                 :: "r"(d), "l"(src) : "memory");
                }
            }
        }
    }
    asm volatile("cp.async.commit_group;" ::: "memory");
}

// ---- circuit helpers --------------------------------------------------------
template <int S>
__device__ __forceinline__ void apply1q(float re[16], float im[16],
                                        float u00r, float u00i,
                                        float u01r, float u01i,
                                        float u10r, float u10i,
                                        float u11r, float u11i) {
#pragma unroll
    for (int a = 0; a < 16; ++a) {
        if (a & S) continue;
        const int b = a + S;
        const float x0r = re[a], x0i = im[a];
        const float x1r = re[b], x1i = im[b];
        re[a] = u00r * x0r - u00i * x0i + u01r * x1r - u01i * x1i;
        im[a] = u00r * x0i + u00i * x0r + u01r * x1i + u01i * x1r;
        re[b] = u10r * x0r - u10i * x0i + u11r * x1r - u11i * x1i;
        im[b] = u10r * x0i + u10i * x0r + u11r * x1i + u11i * x1r;
    }
}

template <int SC, int ST>
__device__ __forceinline__ void apply_cnot(float re[16], float im[16]) {
#pragma unroll
    for (int a = 0; a < 16; ++a) {
        if ((a & SC) && !(a & ST)) {
            const int b = a + ST;
            float t;
            t = re[a]; re[a] = re[b]; re[b] = t;
            t = im[a]; im[a] = im[b]; im[b] = t;
        }
    }
}

// smem layout (dynamic): stage0[10752] | stage1[10752] | pooled[256*17]
#define SM_STAGE1 10752
#define SM_POOLED 21504
#define SMEM_FLOATS (21504 + 256 * 17)
#define SMEM_BYTES (SMEM_FLOATS * 4)

__global__ __launch_bounds__(THREADS) void qfc_fused(
    const float* __restrict__ x,
    const float* __restrict__ enc_w, const float* __restrict__ enc_b,
    const float* __restrict__ qparams,
    const float* __restrict__ cls_w, const float* __restrict__ cls_b,
    const float* __restrict__ bn_gamma, const float* __restrict__ bn_beta,
    float* __restrict__ out,
    int B, int ntiles, int nblk)
{
    extern __shared__ float smem[];
    float* pooled = smem + SM_POOLED;

    __shared__ float sg[12][8];
    __shared__ float sred[8][8];
    __shared__ float sscale[4], sshift[4];

    const int tid = threadIdx.x;

    // --- precompute the 12 Rot gates ---
    if (tid < 12) {
        const float phi = qparams[tid * 3 + 0];
        const float th  = qparams[tid * 3 + 1];
        const float om  = qparams[tid * 3 + 2];
        float sp, cp, smn, cmn, st, ct;
        sincosf(0.5f * (phi + om), &sp, &cp);
        sincosf(0.5f * (phi - om), &smn, &cmn);
        sincosf(0.5f * th, &st, &ct);
        sg[tid][0] =  ct * cp;   sg[tid][1] = -ct * sp;    // U00
        sg[tid][2] = -st * cmn;  sg[tid][3] = -st * smn;   // U01
        sg[tid][4] =  st * cmn;  sg[tid][5] = -st * smn;   // U10
        sg[tid][6] =  ct * cp;   sg[tid][7] =  ct * sp;    // U11
    }
    __syncthreads();

    const float4* x4 = reinterpret_cast<const float4*>(x);

    float4 o0 = make_float4(0.f, 0.f, 0.f, 0.f);   // tile-0 result (registers)
    float acc8[8];
#pragma unroll
    for (int j = 0; j < 8; ++j) acc8[j] = 0.f;

    for (int tile = blockIdx.x; tile < ntiles; tile += nblk) {
        const int b0 = tile * 256;

        issue_chunk(x4, b0, 0, B, smem, tid);
        issue_chunk(x4, b0, 1, B, smem + SM_STAGE1, tid);

        // --- 16 chunks: wait, pool, issue next (double-buffered) ---
        for (int c = 0; c < 16; ++c) {
            asm volatile("cp.async.wait_group 1;" ::: "memory");
            __syncthreads();
            float* stb = smem + ((c & 1) ? SM_STAGE1 : 0);

            const int sl = tid >> 4;
            const int f  = tid & 15;
            const int pr = f >> 2;
            const int pc = f & 3;
            const float* bp = stb + sl * 672 + pr * 168 + pc * 6;
            float a = 0.f;
#pragma unroll
            for (int r = 0; r < 6; ++r)
#pragma unroll
                for (int cc = 0; cc < 6; ++cc)
                    a += bp[r * 28 + cc];
            pooled[(c * 16 + sl) * 17 + f] = a * (1.0f / 36.0f);
            __syncthreads();

            issue_chunk(x4, b0, c + 2, B, stb, tid);   // c+2 reuses buffer (c&1)
        }

        // --- circuit for this thread's sample ---
        const int b = b0 + tid;
        float4 o = make_float4(0.f, 0.f, 0.f, 0.f);
        if (b < B) {
            const float* pf = pooled + tid * 17;

            float z[4];
#pragma unroll
            for (int w = 0; w < 4; ++w) {
                float acc = __ldg(enc_b + w);
#pragma unroll
                for (int f = 0; f < 16; ++f) acc += pf[f] * __ldg(enc_w + w * 16 + f);
                z[w] = acc;
            }

            float cw[4], sw[4];
#pragma unroll
            for (int w = 0; w < 4; ++w) __sincosf(0.5f * z[w], &sw[w], &cw[w]);

            float re[16], im[16];
#pragma unroll
            for (int idx = 0; idx < 16; ++idx) {
                const float p = (idx & 8 ? sw[0] : cw[0]) *
                                (idx & 4 ? sw[1] : cw[1]) *
                                (idx & 2 ? sw[2] : cw[2]) *
                                (idx & 1 ? sw[3] : cw[3]);
                const int m = __popc(idx) & 3;
                re[idx] = (m == 0) ? p : ((m == 2) ? -p : 0.f);
                im[idx] = (m == 1) ? -p : ((m == 3) ? p : 0.f);
            }

#pragma unroll
            for (int layer = 0; layer < 3; ++layer) {
                const float* g;
                g = sg[layer * 4 + 0];
                apply1q<8>(re, im, g[0], g[1], g[2], g[3], g[4], g[5], g[6], g[7]);
                g = sg[layer * 4 + 1];
                apply1q<4>(re, im, g[0], g[1], g[2], g[3], g[4], g[5], g[6], g[7]);
                g = sg[layer * 4 + 2];
                apply1q<2>(re, im, g[0], g[1], g[2], g[3], g[4], g[5], g[6], g[7]);
                g = sg[layer * 4 + 3];
                apply1q<1>(re, im, g[0], g[1], g[2], g[3], g[4], g[5], g[6], g[7]);
                apply_cnot<8, 4>(re, im);
                apply_cnot<4, 2>(re, im);
                apply_cnot<2, 1>(re, im);
            }

            float prob[16];
#pragma unroll
            for (int i = 0; i < 16; ++i) prob[i] = re[i] * re[i] + im[i] * im[i];

            float ev[4];
#pragma unroll
            for (int w = 0; w < 4; ++w) {
                const int s = 8 >> w;
                float e = 0.f;
#pragma unroll
                for (int i = 0; i < 16; ++i) e += (i & s) ? -prob[i] : prob[i];
                ev[w] = e;
            }

            float* op = &o.x;
#pragma unroll
            for (int oo = 0; oo < 4; ++oo) {
                float acc = __ldg(cls_b + oo);
#pragma unroll
                for (int w = 0; w < 4; ++w) acc += ev[w] * __ldg(cls_w + oo * 4 + w);
                op[oo] = acc;
            }
        }

        if (tile == blockIdx.x) {
            o0 = o;                      // keep first tile in registers
        } else if (b < B) {
            reinterpret_cast<float4*>(out)[b] = o;   // raw pre-BN, fixed later
        }

        acc8[0] += o.x;       acc8[1] += o.y;
        acc8[2] += o.z;       acc8[3] += o.w;
        acc8[4] += o.x * o.x; acc8[5] += o.y * o.y;
        acc8[6] += o.z * o.z; acc8[7] += o.w * o.w;
    }

    // --- per-block BN partials ---
#pragma unroll
    for (int j = 0; j < 8; ++j) {
#pragma unroll
        for (int m = 1; m < 32; m <<= 1)
            acc8[j] += __shfl_xor_sync(0xffffffffu, acc8[j], m);
    }
    const int warpid = tid >> 5;
    if ((tid & 31) == 0) {
#pragma unroll
        for (int j = 0; j < 8; ++j) sred[warpid][j] = acc8[j];
    }
    __syncthreads();
    if (tid < 8) {
        float s = 0.f;
#pragma unroll
        for (int k = 0; k < 8; ++k) s += sred[k][tid];
        g_partial[blockIdx.x * 8 + tid] = s;
    }
    __threadfence();
    __syncthreads();

    // --- software global barrier (monotonic counter; graph-replay safe) ---
    if (tid == 0) {
        const unsigned ticket = atomicAdd(&g_bar, 1u);
        const unsigned target = (ticket / (unsigned)nblk + 1u) * (unsigned)nblk;
        while (atomicAdd(&g_bar, 0u) < target) __nanosleep(64);
    }
    __syncthreads();
    __threadfence();

    // --- finalize BN scale/shift (redundant per block) ---
    if (tid < 64) {
        const int j = tid & 7;
        const int g = tid >> 3;
        float s = 0.f;
        for (int k = g; k < nblk; k += 8) s += g_partial[k * 8 + j];
        sred[g][j] = s;
    }
    __syncthreads();
    if (tid < 4) {
        float sum = 0.f, sq = 0.f;
#pragma unroll
        for (int k = 0; k < 8; ++k) { sum += sred[k][tid]; sq += sred[k][tid + 4]; }
        const float invB = 1.0f / (float)B;
        const float mu  = sum * invB;
        const float var = sq * invB - mu * mu;
        const float sc  = bn_gamma[tid] * rsqrtf(var + 1e-5f);
        sscale[tid] = sc;
        sshift[tid] = bn_beta[tid] - mu * sc;
    }
    __syncthreads();

    // --- apply BN: tile 0 straight from registers ---
    {
        const int b = blockIdx.x * 256 + tid;
        if (b < B) {
            float4 v = o0;
            v.x = v.x * sscale[0] + sshift[0];
            v.y = v.y * sscale[1] + sshift[1];
            v.z = v.z * sscale[2] + sshift[2];
            v.w = v.w * sscale[3] + sshift[3];
            reinterpret_cast<float4*>(out)[b] = v;
        }
    }
    // --- extra tiles (only if B > 256*nblk): re-read raw out and fix ---
    for (int tile = blockIdx.x + nblk; tile < ntiles; tile += nblk) {
        const int b = tile * 256 + tid;
        if (b < B) {
            float4 v = reinterpret_cast<float4*>(out)[b];
            v.x = v.x * sscale[0] + sshift[0];
            v.y = v.y * sscale[1] + sshift[1];
            v.z = v.z * sscale[2] + sshift[2];
            v.w = v.w * sscale[3] + sshift[3];
            reinterpret_cast<float4*>(out)[b] = v;
        }
    }
}

extern "C" void kernel_launch(void* const* d_in, const int* in_sizes, int n_in,
                              void* d_out, int out_size)
{
    const float* x        = (const float*)d_in[0];
    const float* enc_w    = (const float*)d_in[1];
    const float* enc_b    = (const float*)d_in[2];
    const float* qparams  = (const float*)d_in[3];
    const float* cls_w    = (const float*)d_in[4];
    const float* cls_b    = (const float*)d_in[5];
    const float* bn_gamma = (const float*)d_in[6];
    const float* bn_beta  = (const float*)d_in[7];
    float* out = (float*)d_out;

    const int B = in_sizes[0] / 784;
    const int ntiles = (B + 255) / 256;
    const int nblk = (ntiles < NBLK_MAX) ? ntiles : NBLK_MAX;

    cudaFuncSetAttribute(qfc_fused, cudaFuncAttributeMaxDynamicSharedMemorySize,
                         SMEM_BYTES);
    qfc_fused<<<nblk, THREADS, SMEM_BYTES>>>(
        x, enc_w, enc_b, qparams, cls_w, cls_b, bn_gamma, bn_beta, out,
        B, ntiles, nblk);
}

// round 5
// speedup vs baseline: 1.3855x; 1.0648x over previous
#include <cuda_runtime.h>
#include <cstdint>

// ---------------------------------------------------------------------------
// R5: warp-autonomous streaming. Each warp owns 32 samples with a private
//     double-buffered cp.async pipeline (2-sample chunks) -> NO block barriers
//     in the streaming loop. 128-thread blocks, grid=256 (2 blocks/SM).
//     Vectorized pooling (float4+float2). Fused BN via global counter barrier.
// ---------------------------------------------------------------------------

#define NBLK_MAX 256
#define THREADS 128

__device__ float g_partial[NBLK_MAX * 8];
__device__ unsigned g_bar = 0;

__device__ __forceinline__ uint32_t smem_u32(const void* p) {
    return (uint32_t)__cvta_generic_to_shared(p);
}

// Per-warp: issue one 2-sample chunk (2 x 168 float4) into buf, commit group.
__device__ __forceinline__ void issue_chunk_warp(
    const float4* __restrict__ x4, int gbase, int B,
    float* buf, int lane)
{
#pragma unroll
    for (int k = 0; k < 11; ++k) {
        const int i = lane + k * 32;
        if (i < 336) {
            const int s = (i >= 168) ? 1 : 0;
            const int o = i - s * 168;
            const int gs = gbase + s;
            if (gs < B) {
                const uint32_t d = smem_u32(buf + s * 672 + o * 4);
                const float4* src = x4 + (size_t)gs * 196 + o;
                asm volatile("cp.async.cg.shared.global [%0], [%1], 16;"
                             :: "r"(d), "l"(src) : "memory");
            }
        }
    }
    asm volatile("cp.async.commit_group;" ::: "memory");
}

// ---- circuit helpers --------------------------------------------------------
template <int S>
__device__ __forceinline__ void apply1q(float re[16], float im[16],
                                        float u00r, float u00i,
                                        float u01r, float u01i,
                                        float u10r, float u10i,
                                        float u11r, float u11i) {
#pragma unroll
    for (int a = 0; a < 16; ++a) {
        if (a & S) continue;
        const int b = a + S;
        const float x0r = re[a], x0i = im[a];
        const float x1r = re[b], x1i = im[b];
        re[a] = u00r * x0r - u00i * x0i + u01r * x1r - u01i * x1i;
        im[a] = u00r * x0i + u00i * x0r + u01r * x1i + u01i * x1r;
        re[b] = u10r * x0r - u10i * x0i + u11r * x1r - u11i * x1i;
        im[b] = u10r * x0i + u10i * x0r + u11r * x1i + u11i * x1r;
    }
}

template <int SC, int ST>
__device__ __forceinline__ void apply_cnot(float re[16], float im[16]) {
#pragma unroll
    for (int a = 0; a < 16; ++a) {
        if ((a & SC) && !(a & ST)) {
            const int b = a + ST;
            float t;
            t = re[a]; re[a] = re[b]; re[b] = t;
            t = im[a]; im[a] = im[b]; im[b] = t;
        }
    }
}

// dynamic smem layout (floats):
//   warp w buffers: [w*2688 , w*2688+2688)   (2 bufs x 2 samples x 672)
//   pooled:          [10752 , 10752 + 128*17)
#define SM_POOLED 10752
#define SMEM_FLOATS (10752 + 128 * 17)
#define SMEM_BYTES (SMEM_FLOATS * 4)

__global__ __launch_bounds__(THREADS) void qfc_fused(
    const float* __restrict__ x,
    const float* __restrict__ enc_w, const float* __restrict__ enc_b,
    const float* __restrict__ qparams,
    const float* __restrict__ cls_w, const float* __restrict__ cls_b,
    const float* __restrict__ bn_gamma, const float* __restrict__ bn_beta,
    float* __restrict__ out,
    int B, int ntiles, int nblk)
{
    extern __shared__ float smem[];
    float* pooled = smem + SM_POOLED;

    __shared__ float sg[12][8];
    __shared__ float sred[8][8];
    __shared__ float sscale[4], sshift[4];

    const int tid  = threadIdx.x;
    const int w    = tid >> 5;
    const int lane = tid & 31;

    // --- precompute the 12 Rot gates ---
    if (tid < 12) {
        const float phi = qparams[tid * 3 + 0];
        const float th  = qparams[tid * 3 + 1];
        const float om  = qparams[tid * 3 + 2];
        float sp, cp, smn, cmn, st, ct;
        sincosf(0.5f * (phi + om), &sp, &cp);
        sincosf(0.5f * (phi - om), &smn, &cmn);
        sincosf(0.5f * th, &st, &ct);
        sg[tid][0] =  ct * cp;   sg[tid][1] = -ct * sp;    // U00
        sg[tid][2] = -st * cmn;  sg[tid][3] = -st * smn;   // U01
        sg[tid][4] =  st * cmn;  sg[tid][5] = -st * smn;   // U10
        sg[tid][6] =  ct * cp;   sg[tid][7] =  ct * sp;    // U11
    }
    __syncthreads();

    const float4* x4 = reinterpret_cast<const float4*>(x);
    float* wbuf0 = smem + w * 2688;
    float* wbuf1 = wbuf0 + 1344;

    // pooling lane roles
    const int ps = lane >> 4;            // sample within chunk (0/1)
    const int pf = lane & 15;            // feature
    const int ppr = pf >> 2;
    const int ppc = pf & 3;
    const int poff = ps * 672 + ppr * 168 + ppc * 6;
    const bool pcodd = (ppc & 1);

    float4 o0 = make_float4(0.f, 0.f, 0.f, 0.f);
    float acc8[8];
#pragma unroll
    for (int j = 0; j < 8; ++j) acc8[j] = 0.f;

    for (int tile = blockIdx.x; tile < ntiles; tile += nblk) {
        const int b0 = tile * 128;
        const int wg = b0 + w * 32;      // this warp's first global sample

        // --- warp-private pipeline over 16 chunks of 2 samples ---
        issue_chunk_warp(x4, wg + 0, B, wbuf0, lane);
        issue_chunk_warp(x4, wg + 2, B, wbuf1, lane);

#pragma unroll 1
        for (int c = 0; c < 16; ++c) {
            asm volatile("cp.async.wait_group 1;" ::: "memory");
            __syncwarp();
            const float* buf = (c & 1) ? wbuf1 : wbuf0;

            // pool this lane's (sample, feature)
            const float* bp = buf + poff;
            float a = 0.f;
            if (pcodd) {
#pragma unroll
                for (int r = 0; r < 6; ++r) {
                    const float* rp = bp + r * 28;
                    const float2 u = *reinterpret_cast<const float2*>(rp);
                    const float4 v = *reinterpret_cast<const float4*>(rp + 2);
                    a += u.x + u.y + v.x + v.y + v.z + v.w;
                }
            } else {
#pragma unroll
                for (int r = 0; r < 6; ++r) {
                    const float* rp = bp + r * 28;
                    const float4 v = *reinterpret_cast<const float4*>(rp);
                    const float2 u = *reinterpret_cast<const float2*>(rp + 4);
                    a += v.x + v.y + v.z + v.w + u.x + u.y;
                }
            }
            pooled[(w * 32 + c * 2 + ps) * 17 + pf] = a * (1.0f / 36.0f);
            __syncwarp();

            // refill this buffer with chunk c+2 (same warp -> no race)
            issue_chunk_warp(x4, wg + (c + 2) * 2, (c + 2 < 16) ? B : 0,
                             (c & 1) ? wbuf1 : wbuf0, lane);
        }
        __syncthreads();   // pooled[] complete across warps

        // --- circuit: one thread per sample ---
        const int b = b0 + tid;
        float4 o = make_float4(0.f, 0.f, 0.f, 0.f);
        if (b < B) {
            const float* pf2 = pooled + tid * 17;

            float z[4];
#pragma unroll
            for (int ww = 0; ww < 4; ++ww) {
                float acc = __ldg(enc_b + ww);
#pragma unroll
                for (int f = 0; f < 16; ++f) acc += pf2[f] * __ldg(enc_w + ww * 16 + f);
                z[ww] = acc;
            }

            float cw[4], sw[4];
#pragma unroll
            for (int ww = 0; ww < 4; ++ww) __sincosf(0.5f * z[ww], &sw[ww], &cw[ww]);

            float re[16], im[16];
#pragma unroll
            for (int idx = 0; idx < 16; ++idx) {
                const float p = (idx & 8 ? sw[0] : cw[0]) *
                                (idx & 4 ? sw[1] : cw[1]) *
                                (idx & 2 ? sw[2] : cw[2]) *
                                (idx & 1 ? sw[3] : cw[3]);
                const int m = __popc(idx) & 3;
                re[idx] = (m == 0) ? p : ((m == 2) ? -p : 0.f);
                im[idx] = (m == 1) ? -p : ((m == 3) ? p : 0.f);
            }

#pragma unroll
            for (int layer = 0; layer < 3; ++layer) {
                const float* g;
                g = sg[layer * 4 + 0];
                apply1q<8>(re, im, g[0], g[1], g[2], g[3], g[4], g[5], g[6], g[7]);
                g = sg[layer * 4 + 1];
                apply1q<4>(re, im, g[0], g[1], g[2], g[3], g[4], g[5], g[6], g[7]);
                g = sg[layer * 4 + 2];
                apply1q<2>(re, im, g[0], g[1], g[2], g[3], g[4], g[5], g[6], g[7]);
                g = sg[layer * 4 + 3];
                apply1q<1>(re, im, g[0], g[1], g[2], g[3], g[4], g[5], g[6], g[7]);
                apply_cnot<8, 4>(re, im);
                apply_cnot<4, 2>(re, im);
                apply_cnot<2, 1>(re, im);
            }

            float prob[16];
#pragma unroll
            for (int i = 0; i < 16; ++i) prob[i] = re[i] * re[i] + im[i] * im[i];

            float ev[4];
#pragma unroll
            for (int ww = 0; ww < 4; ++ww) {
                const int s = 8 >> ww;
                float e = 0.f;
#pragma unroll
                for (int i = 0; i < 16; ++i) e += (i & s) ? -prob[i] : prob[i];
                ev[ww] = e;
            }

            float* op = &o.x;
#pragma unroll
            for (int oo = 0; oo < 4; ++oo) {
                float acc = __ldg(cls_b + oo);
#pragma unroll
                for (int ww = 0; ww < 4; ++ww) acc += ev[ww] * __ldg(cls_w + oo * 4 + ww);
                op[oo] = acc;
            }
        }

        if (tile == blockIdx.x) {
            o0 = o;
        } else if (b < B) {
            reinterpret_cast<float4*>(out)[b] = o;   // raw; fixed after barrier
        }

        acc8[0] += o.x;       acc8[1] += o.y;
        acc8[2] += o.z;       acc8[3] += o.w;
        acc8[4] += o.x * o.x; acc8[5] += o.y * o.y;
        acc8[6] += o.z * o.z; acc8[7] += o.w * o.w;
    }

    // --- per-block BN partials ---
#pragma unroll
    for (int j = 0; j < 8; ++j) {
#pragma unroll
        for (int m = 1; m < 32; m <<= 1)
            acc8[j] += __shfl_xor_sync(0xffffffffu, acc8[j], m);
    }
    if (lane == 0) {
#pragma unroll
        for (int j = 0; j < 8; ++j) sred[w][j] = acc8[j];
    }
    __syncthreads();
    if (tid < 8) {
        float s = 0.f;
#pragma unroll
        for (int k = 0; k < 4; ++k) s += sred[k][tid];
        g_partial[blockIdx.x * 8 + tid] = s;
    }
    __threadfence();
    __syncthreads();

    // --- software global barrier (monotonic counter; graph-replay safe) ---
    if (tid == 0) {
        const unsigned ticket = atomicAdd(&g_bar, 1u);
        const unsigned target = (ticket / (unsigned)nblk + 1u) * (unsigned)nblk;
        while (atomicAdd(&g_bar, 0u) < target) __nanosleep(64);
    }
    __syncthreads();
    __threadfence();

    // --- finalize BN scale/shift (redundant per block) ---
    if (tid < 64) {
        const int j = tid & 7;
        const int g = tid >> 3;
        float s = 0.f;
        for (int k = g; k < nblk; k += 8) s += g_partial[k * 8 + j];
        sred[g][j] = s;
    }
    __syncthreads();
    if (tid < 4) {
        float sum = 0.f, sq = 0.f;
#pragma unroll
        for (int k = 0; k < 8; ++k) { sum += sred[k][tid]; sq += sred[k][tid + 4]; }
        const float invB = 1.0f / (float)B;
        const float mu  = sum * invB;
        const float var = sq * invB - mu * mu;
        const float sc  = bn_gamma[tid] * rsqrtf(var + 1e-5f);
        sscale[tid] = sc;
        sshift[tid] = bn_beta[tid] - mu * sc;
    }
    __syncthreads();

    // --- apply BN: first tile straight from registers ---
    {
        const int b = blockIdx.x * 128 + tid;
        if (b < B) {
            float4 v = o0;
            v.x = v.x * sscale[0] + sshift[0];
            v.y = v.y * sscale[1] + sshift[1];
            v.z = v.z * sscale[2] + sshift[2];
            v.w = v.w * sscale[3] + sshift[3];
            reinterpret_cast<float4*>(out)[b] = v;
        }
    }
    for (int tile = blockIdx.x + nblk; tile < ntiles; tile += nblk) {
        const int b = tile * 128 + tid;
        if (b < B) {
            float4 v = reinterpret_cast<float4*>(out)[b];
            v.x = v.x * sscale[0] + sshift[0];
            v.y = v.y * sscale[1] + sshift[1];
            v.z = v.z * sscale[2] + sshift[2];
            v.w = v.w * sscale[3] + sshift[3];
            reinterpret_cast<float4*>(out)[b] = v;
        }
    }
}

extern "C" void kernel_launch(void* const* d_in, const int* in_sizes, int n_in,
                              void* d_out, int out_size)
{
    const float* x        = (const float*)d_in[0];
    const float* enc_w    = (const float*)d_in[1];
    const float* enc_b    = (const float*)d_in[2];
    const float* qparams  = (const float*)d_in[3];
    const float* cls_w    = (const float*)d_in[4];
    const float* cls_b    = (const float*)d_in[5];
    const float* bn_gamma = (const float*)d_in[6];
    const float* bn_beta  = (const float*)d_in[7];
    float* out = (float*)d_out;

    const int B = in_sizes[0] / 784;
    const int ntiles = (B + 127) / 128;
    const int nblk = (ntiles < NBLK_MAX) ? ntiles : NBLK_MAX;

    cudaFuncSetAttribute(qfc_fused, cudaFuncAttributeMaxDynamicSharedMemorySize,
                         SMEM_BYTES);
    qfc_fused<<<nblk, THREADS, SMEM_BYTES>>>(
        x, enc_w, enc_b, qparams, cls_w, cls_b, bn_gamma, bn_beta, out,
        B, ntiles, nblk);
}

// round 6
// speedup vs baseline: 1.5541x; 1.1216x over previous
#include <cuda_runtime.h>
#include <cstdint>

// ---------------------------------------------------------------------------
// R6: R5 + 4-deep warp-private cp.async pipeline (wait_group 3).
//     Each warp keeps 3 chunks (16KB) in flight while pooling the 4th:
//     DRAM latency fully hidden per-warp instead of relying on warp count.
// ---------------------------------------------------------------------------

#define NBLK_MAX 256
#define THREADS 128

__device__ float g_partial[NBLK_MAX * 8];
__device__ unsigned g_bar = 0;

__device__ __forceinline__ uint32_t smem_u32(const void* p) {
    return (uint32_t)__cvta_generic_to_shared(p);
}

// Per-warp: issue one 2-sample chunk (2 x 168 float4) into buf, commit group.
__device__ __forceinline__ void issue_chunk_warp(
    const float4* __restrict__ x4, int gbase, int B,
    float* buf, int lane)
{
#pragma unroll
    for (int k = 0; k < 11; ++k) {
        const int i = lane + k * 32;
        if (i < 336) {
            const int s = (i >= 168) ? 1 : 0;
            const int o = i - s * 168;
            const int gs = gbase + s;
            if (gs < B) {
                const uint32_t d = smem_u32(buf + s * 672 + o * 4);
                const float4* src = x4 + (size_t)gs * 196 + o;
                asm volatile("cp.async.cg.shared.global [%0], [%1], 16;"
                             :: "r"(d), "l"(src) : "memory");
            }
        }
    }
    asm volatile("cp.async.commit_group;" ::: "memory");
}

// ---- circuit helpers --------------------------------------------------------
template <int S>
__device__ __forceinline__ void apply1q(float re[16], float im[16],
                                        float u00r, float u00i,
                                        float u01r, float u01i,
                                        float u10r, float u10i,
                                        float u11r, float u11i) {
#pragma unroll
    for (int a = 0; a < 16; ++a) {
        if (a & S) continue;
        const int b = a + S;
        const float x0r = re[a], x0i = im[a];
        const float x1r = re[b], x1i = im[b];
        re[a] = u00r * x0r - u00i * x0i + u01r * x1r - u01i * x1i;
        im[a] = u00r * x0i + u00i * x0r + u01r * x1i + u01i * x1r;
        re[b] = u10r * x0r - u10i * x0i + u11r * x1r - u11i * x1i;
        im[b] = u10r * x0i + u10i * x0r + u11r * x1i + u11i * x1r;
    }
}

template <int SC, int ST>
__device__ __forceinline__ void apply_cnot(float re[16], float im[16]) {
#pragma unroll
    for (int a = 0; a < 16; ++a) {
        if ((a & SC) && !(a & ST)) {
            const int b = a + ST;
            float t;
            t = re[a]; re[a] = re[b]; re[b] = t;
            t = im[a]; im[a] = im[b]; im[b] = t;
        }
    }
}

// dynamic smem layout (floats):
//   warp w: 4 buffers x 1344 floats at w*5376
//   pooled: [21504, 21504 + 128*17)
#define SM_POOLED 21504
#define SMEM_FLOATS (21504 + 128 * 17)
#define SMEM_BYTES (SMEM_FLOATS * 4)

__global__ __launch_bounds__(THREADS) void qfc_fused(
    const float* __restrict__ x,
    const float* __restrict__ enc_w, const float* __restrict__ enc_b,
    const float* __restrict__ qparams,
    const float* __restrict__ cls_w, const float* __restrict__ cls_b,
    const float* __restrict__ bn_gamma, const float* __restrict__ bn_beta,
    float* __restrict__ out,
    int B, int ntiles, int nblk)
{
    extern __shared__ float smem[];
    float* pooled = smem + SM_POOLED;

    __shared__ float sg[12][8];
    __shared__ float sred[8][8];
    __shared__ float sscale[4], sshift[4];

    const int tid  = threadIdx.x;
    const int w    = tid >> 5;
    const int lane = tid & 31;

    // --- precompute the 12 Rot gates ---
    if (tid < 12) {
        const float phi = qparams[tid * 3 + 0];
        const float th  = qparams[tid * 3 + 1];
        const float om  = qparams[tid * 3 + 2];
        float sp, cp, smn, cmn, st, ct;
        sincosf(0.5f * (phi + om), &sp, &cp);
        sincosf(0.5f * (phi - om), &smn, &cmn);
        sincosf(0.5f * th, &st, &ct);
        sg[tid][0] =  ct * cp;   sg[tid][1] = -ct * sp;    // U00
        sg[tid][2] = -st * cmn;  sg[tid][3] = -st * smn;   // U01
        sg[tid][4] =  st * cmn;  sg[tid][5] = -st * smn;   // U10
        sg[tid][6] =  ct * cp;   sg[tid][7] =  ct * sp;    // U11
    }
    __syncthreads();

    const float4* x4 = reinterpret_cast<const float4*>(x);
    float* wbase = smem + w * 5376;      // 4 buffers x 1344 floats

    // pooling lane roles
    const int ps = lane >> 4;            // sample within chunk (0/1)
    const int pf = lane & 15;            // feature
    const int ppr = pf >> 2;
    const int ppc = pf & 3;
    const int poff = ps * 672 + ppr * 168 + ppc * 6;
    const bool pcodd = (ppc & 1);

    float4 o0 = make_float4(0.f, 0.f, 0.f, 0.f);
    float acc8[8];
#pragma unroll
    for (int j = 0; j < 8; ++j) acc8[j] = 0.f;

    for (int tile = blockIdx.x; tile < ntiles; tile += nblk) {
        const int b0 = tile * 128;
        const int wg = b0 + w * 32;      // this warp's first global sample

        // --- 4-deep warp-private pipeline over 16 chunks of 2 samples ---
        issue_chunk_warp(x4, wg + 0, B, wbase + 0 * 1344, lane);
        issue_chunk_warp(x4, wg + 2, B, wbase + 1 * 1344, lane);
        issue_chunk_warp(x4, wg + 4, B, wbase + 2 * 1344, lane);
        issue_chunk_warp(x4, wg + 6, B, wbase + 3 * 1344, lane);

#pragma unroll 1
        for (int c = 0; c < 16; ++c) {
            asm volatile("cp.async.wait_group 3;" ::: "memory");
            __syncwarp();
            float* buf = wbase + (c & 3) * 1344;

            // pool this lane's (sample, feature)
            const float* bp = buf + poff;
            float a = 0.f;
            if (pcodd) {
#pragma unroll
                for (int r = 0; r < 6; ++r) {
                    const float* rp = bp + r * 28;
                    const float2 u = *reinterpret_cast<const float2*>(rp);
                    const float4 v = *reinterpret_cast<const float4*>(rp + 2);
                    a += u.x + u.y + v.x + v.y + v.z + v.w;
                }
            } else {
#pragma unroll
                for (int r = 0; r < 6; ++r) {
                    const float* rp = bp + r * 28;
                    const float4 v = *reinterpret_cast<const float4*>(rp);
                    const float2 u = *reinterpret_cast<const float2*>(rp + 4);
                    a += v.x + v.y + v.z + v.w + u.x + u.y;
                }
            }
            pooled[(w * 32 + c * 2 + ps) * 17 + pf] = a * (1.0f / 36.0f);
            __syncwarp();

            // refill this buffer with chunk c+4 (same warp -> no race)
            issue_chunk_warp(x4, wg + (c + 4) * 2, (c + 4 < 16) ? B : 0,
                             buf, lane);
        }
        __syncthreads();   // pooled[] complete across warps

        // --- circuit: one thread per sample ---
        const int b = b0 + tid;
        float4 o = make_float4(0.f, 0.f, 0.f, 0.f);
        if (b < B) {
            const float* pf2 = pooled + tid * 17;

            float z[4];
#pragma unroll
            for (int ww = 0; ww < 4; ++ww) {
                float acc = __ldg(enc_b + ww);
#pragma unroll
                for (int f = 0; f < 16; ++f) acc += pf2[f] * __ldg(enc_w + ww * 16 + f);
                z[ww] = acc;
            }

            float cw[4], sw[4];
#pragma unroll
            for (int ww = 0; ww < 4; ++ww) __sincosf(0.5f * z[ww], &sw[ww], &cw[ww]);

            float re[16], im[16];
#pragma unroll
            for (int idx = 0; idx < 16; ++idx) {
                const float p = (idx & 8 ? sw[0] : cw[0]) *
                                (idx & 4 ? sw[1] : cw[1]) *
                                (idx & 2 ? sw[2] : cw[2]) *
                                (idx & 1 ? sw[3] : cw[3]);
                const int m = __popc(idx) & 3;
                re[idx] = (m == 0) ? p : ((m == 2) ? -p : 0.f);
                im[idx] = (m == 1) ? -p : ((m == 3) ? p : 0.f);
            }

#pragma unroll
            for (int layer = 0; layer < 3; ++layer) {
                const float* g;
                g = sg[layer * 4 + 0];
                apply1q<8>(re, im, g[0], g[1], g[2], g[3], g[4], g[5], g[6], g[7]);
                g = sg[layer * 4 + 1];
                apply1q<4>(re, im, g[0], g[1], g[2], g[3], g[4], g[5], g[6], g[7]);
                g = sg[layer * 4 + 2];
                apply1q<2>(re, im, g[0], g[1], g[2], g[3], g[4], g[5], g[6], g[7]);
                g = sg[layer * 4 + 3];
                apply1q<1>(re, im, g[0], g[1], g[2], g[3], g[4], g[5], g[6], g[7]);
                apply_cnot<8, 4>(re, im);
                apply_cnot<4, 2>(re, im);
                apply_cnot<2, 1>(re, im);
            }

            float prob[16];
#pragma unroll
            for (int i = 0; i < 16; ++i) prob[i] = re[i] * re[i] + im[i] * im[i];

            float ev[4];
#pragma unroll
            for (int ww = 0; ww < 4; ++ww) {
                const int s = 8 >> ww;
                float e = 0.f;
#pragma unroll
                for (int i = 0; i < 16; ++i) e += (i & s) ? -prob[i] : prob[i];
                ev[ww] = e;
            }

            float* op = &o.x;
#pragma unroll
            for (int oo = 0; oo < 4; ++oo) {
                float acc = __ldg(cls_b + oo);
#pragma unroll
                for (int ww = 0; ww < 4; ++ww) acc += ev[ww] * __ldg(cls_w + oo * 4 + ww);
                op[oo] = acc;
            }
        }

        if (tile == blockIdx.x) {
            o0 = o;
        } else if (b < B) {
            reinterpret_cast<float4*>(out)[b] = o;   // raw; fixed after barrier
        }

        acc8[0] += o.x;       acc8[1] += o.y;
        acc8[2] += o.z;       acc8[3] += o.w;
        acc8[4] += o.x * o.x; acc8[5] += o.y * o.y;
        acc8[6] += o.z * o.z; acc8[7] += o.w * o.w;
    }

    // --- per-block BN partials ---
#pragma unroll
    for (int j = 0; j < 8; ++j) {
#pragma unroll
        for (int m = 1; m < 32; m <<= 1)
            acc8[j] += __shfl_xor_sync(0xffffffffu, acc8[j], m);
    }
    if (lane == 0) {
#pragma unroll
        for (int j = 0; j < 8; ++j) sred[w][j] = acc8[j];
    }
    __syncthreads();
    if (tid < 8) {
        float s = 0.f;
#pragma unroll
        for (int k = 0; k < 4; ++k) s += sred[k][tid];
        g_partial[blockIdx.x * 8 + tid] = s;
    }
    __threadfence();
    __syncthreads();

    // --- software global barrier (monotonic counter; graph-replay safe) ---
    if (tid == 0) {
        const unsigned ticket = atomicAdd(&g_bar, 1u);
        const unsigned target = (ticket / (unsigned)nblk + 1u) * (unsigned)nblk;
        while (atomicAdd(&g_bar, 0u) < target) __nanosleep(64);
    }
    __syncthreads();
    __threadfence();

    // --- finalize BN scale/shift (redundant per block) ---
    if (tid < 64) {
        const int j = tid & 7;
        const int g = tid >> 3;
        float s = 0.f;
        for (int k = g; k < nblk; k += 8) s += g_partial[k * 8 + j];
        sred[g][j] = s;
    }
    __syncthreads();
    if (tid < 4) {
        float sum = 0.f, sq = 0.f;
#pragma unroll
        for (int k = 0; k < 8; ++k) { sum += sred[k][tid]; sq += sred[k][tid + 4]; }
        const float invB = 1.0f / (float)B;
        const float mu  = sum * invB;
        const float var = sq * invB - mu * mu;
        const float sc  = bn_gamma[tid] * rsqrtf(var + 1e-5f);
        sscale[tid] = sc;
        sshift[tid] = bn_beta[tid] - mu * sc;
    }
    __syncthreads();

    // --- apply BN: first tile straight from registers ---
    {
        const int b = blockIdx.x * 128 + tid;
        if (b < B) {
            float4 v = o0;
            v.x = v.x * sscale[0] + sshift[0];
            v.y = v.y * sscale[1] + sshift[1];
            v.z = v.z * sscale[2] + sshift[2];
            v.w = v.w * sscale[3] + sshift[3];
            reinterpret_cast<float4*>(out)[b] = v;
        }
    }
    for (int tile = blockIdx.x + nblk; tile < ntiles; tile += nblk) {
        const int b = tile * 128 + tid;
        if (b < B) {
            float4 v = reinterpret_cast<float4*>(out)[b];
            v.x = v.x * sscale[0] + sshift[0];
            v.y = v.y * sscale[1] + sshift[1];
            v.z = v.z * sscale[2] + sshift[2];
            v.w = v.w * sscale[3] + sshift[3];
            reinterpret_cast<float4*>(out)[b] = v;
        }
    }
}

extern "C" void kernel_launch(void* const* d_in, const int* in_sizes, int n_in,
                              void* d_out, int out_size)
{
    const float* x        = (const float*)d_in[0];
    const float* enc_w    = (const float*)d_in[1];
    const float* enc_b    = (const float*)d_in[2];
    const float* qparams  = (const float*)d_in[3];
    const float* cls_w    = (const float*)d_in[4];
    const float* cls_b    = (const float*)d_in[5];
    const float* bn_gamma = (const float*)d_in[6];
    const float* bn_beta  = (const float*)d_in[7];
    float* out = (float*)d_out;

    const int B = in_sizes[0] / 784;
    const int ntiles = (B + 127) / 128;
    const int nblk = (ntiles < NBLK_MAX) ? ntiles : NBLK_MAX;

    cudaFuncSetAttribute(qfc_fused, cudaFuncAttributeMaxDynamicSharedMemorySize,
                         SMEM_BYTES);
    qfc_fused<<<nblk, THREADS, SMEM_BYTES>>>(
        x, enc_w, enc_b, qparams, cls_w, cls_b, bn_gamma, bn_beta, out,
        B, ntiles, nblk);
}